// round 15
// baseline (speedup 1.0000x reference)
#include <cuda_runtime.h>
#include <cuda_fp16.h>
#include <cstdint>

// Problem constants
#define NN      8192
#define DD      128
#define BTN     256                // CTA tile rows (n)
#define BTM     128                // CTA tile cols (m)
#define NTN     (NN / BTN)         // 32
#define NTM     (NN / BTM)         // 64
#define NUNITS  (NTN * NTM)        // 2048
#define NCTA    148
#define SCALE   50.0f

// SMEM geometry: padded row stride 272 bytes (136 fp16)
#define SROW    272
#define TA      (BTN * SROW)       // 69632
#define TBB     (BTM * SROW)       // 34816
#define OFF_A(b)   ((b) * TA)
#define OFF_B(b)   (2 * TA + (b) * TBB)
#define SMEM_BYTES (2 * TA + 2 * TBB)  // 208896

// Static device scratch
__device__ __half g_ts_h[NN * DD];
__device__ __half g_sq_h[NN * DD];
__device__ float  g_diag[NN];        // 50 * <ts_n, sq_n> (fp32 exact)
__device__ float  g_rowsum[NN];
__device__ double g_acc[2];
__device__ unsigned int g_cnt;

// ---------------- PTX helpers ----------------
__device__ __forceinline__ void cp16(uint32_t saddr, const void* g) {
    asm volatile("cp.async.cg.shared.global [%0], [%1], 16;" :: "r"(saddr), "l"(g));
}
__device__ __forceinline__ void cp_commit() { asm volatile("cp.async.commit_group;"); }
__device__ __forceinline__ void cp_wait1()  { asm volatile("cp.async.wait_group 1;"); }

__device__ __forceinline__ void ldsm4(uint32_t a, uint32_t& r0, uint32_t& r1,
                                      uint32_t& r2, uint32_t& r3) {
    asm volatile("ldmatrix.sync.aligned.m8n8.x4.shared.b16 {%0,%1,%2,%3}, [%4];"
                 : "=r"(r0), "=r"(r1), "=r"(r2), "=r"(r3) : "r"(a));
}
// fp16-accumulate HMMA
__device__ __forceinline__ void mma16816h(uint32_t* c, const uint32_t* a,
                                          uint32_t b0, uint32_t b1) {
    asm volatile("mma.sync.aligned.m16n8k16.row.col.f16.f16.f16.f16 "
                 "{%0,%1}, {%2,%3,%4,%5}, {%6,%7}, {%0,%1};"
                 : "+r"(c[0]), "+r"(c[1])
                 : "r"(a[0]), "r"(a[1]), "r"(a[2]), "r"(a[3]), "r"(b0), "r"(b1));
}
__device__ __forceinline__ float2 h2_to_f2(uint32_t u) {
    float2 r;
    asm("{\n\t.reg .f16 h0, h1;\n\t"
        "mov.b32 {h0, h1}, %2;\n\t"
        "cvt.f32.f16 %0, h0;\n\t"
        "cvt.f32.f16 %1, h1;\n\t}" : "=f"(r.x), "=f"(r.y) : "r"(u));
    return r;
}

// ---------------- kernel 1: normalize (4 rows/warp) + fp16 out + exact diag ----------------
// 256 blocks x 8 warps x 4 rows = 8192 rows; each warp handles BOTH matrices.
__global__ void __launch_bounds__(256) k_norm(const float* __restrict__ ts,
                                              const float* __restrict__ sq) {
    const int tid = threadIdx.x;
    if (blockIdx.x < 8) {   // zero accumulators
        reinterpret_cast<float4*>(g_rowsum)[blockIdx.x * 256 + tid] =
            make_float4(0.f, 0.f, 0.f, 0.f);
        if (blockIdx.x == 0 && tid == 0) {
            g_acc[0] = 0.0; g_acc[1] = 0.0; g_cnt = 0u;
        }
    }
    const int n0   = blockIdx.x * 32 + (tid >> 5) * 4;
    const int lane = tid & 31;

    float4 a[4], b[4];
    float st[4], sg[4], dt[4];
#pragma unroll
    for (int r = 0; r < 4; ++r) {
        a[r] = reinterpret_cast<const float4*>(ts + (size_t)(n0 + r) * DD)[lane];
        b[r] = reinterpret_cast<const float4*>(sq + (size_t)(n0 + r) * DD)[lane];
    }
#pragma unroll
    for (int r = 0; r < 4; ++r) {
        st[r] = a[r].x * a[r].x + a[r].y * a[r].y + a[r].z * a[r].z + a[r].w * a[r].w;
        sg[r] = b[r].x * b[r].x + b[r].y * b[r].y + b[r].z * b[r].z + b[r].w * b[r].w;
        dt[r] = a[r].x * b[r].x + a[r].y * b[r].y + a[r].z * b[r].z + a[r].w * b[r].w;
    }
#pragma unroll
    for (int o = 16; o; o >>= 1) {
#pragma unroll
        for (int r = 0; r < 4; ++r) {
            st[r] += __shfl_xor_sync(0xffffffffu, st[r], o);
            sg[r] += __shfl_xor_sync(0xffffffffu, sg[r], o);
            dt[r] += __shfl_xor_sync(0xffffffffu, dt[r], o);
        }
    }
#pragma unroll
    for (int r = 0; r < 4; ++r) {
        float it = 1.0f / fmaxf(sqrtf(st[r]), 1e-12f);
        float is = 1.0f / fmaxf(sqrtf(sg[r]), 1e-12f);
        size_t e = (size_t)(n0 + r) * DD + lane * 4;
        *reinterpret_cast<__half2*>(g_ts_h + e)     = __floats2half2_rn(a[r].x * it, a[r].y * it);
        *reinterpret_cast<__half2*>(g_ts_h + e + 2) = __floats2half2_rn(a[r].z * it, a[r].w * it);
        *reinterpret_cast<__half2*>(g_sq_h + e)     = __floats2half2_rn(b[r].x * is, b[r].y * is);
        *reinterpret_cast<__half2*>(g_sq_h + e + 2) = __floats2half2_rn(b[r].z * is, b[r].w * is);
        if (lane == 0)
            g_diag[n0 + r] = dt[r] * it * is * SCALE;
    }
}

// ---------------- tile loaders (256 threads) ----------------
__device__ __forceinline__ void load_A_async(uint32_t s_dst, const __half* g,
                                             int row0, int tid) {
#pragma unroll
    for (int it = 0; it < 16; ++it) {
        int ch  = tid + it * 256;
        int r   = ch >> 4;
        int c16 = ch & 15;
        cp16(s_dst + (uint32_t)(r * SROW + c16 * 16),
             g + (size_t)(row0 + r) * DD + c16 * 8);
    }
}
__device__ __forceinline__ void load_B_async(uint32_t s_dst, const __half* g,
                                             int row0, int tid) {
#pragma unroll
    for (int it = 0; it < 8; ++it) {
        int ch  = tid + it * 256;
        int r   = ch >> 4;
        int c16 = ch & 15;
        cp16(s_dst + (uint32_t)(r * SROW + c16 * 16),
             g + (size_t)(row0 + r) * DD + c16 * 8);
    }
}

// process 1/8 of the previous unit's accumulators
#define PREV_CHUNK(kk)                                                         \
    {                                                                          \
        const int pi = (kk) >> 1, pc0 = ((kk) & 1) * 4;                        \
        _Pragma("unroll")                                                      \
        for (int cb = 0; cb < 4; ++cb) {                                       \
            float2 lo = h2_to_f2(accP[pi][pc0 + cb][0]);                       \
            float2 hi = h2_to_f2(accP[pi][pc0 + cb][1]);                       \
            sums[pi][0] += __expf(fmaf(lo.x, SCALE, -SCALE));                  \
            sums[pi][0] += __expf(fmaf(lo.y, SCALE, -SCALE));                  \
            sums[pi][1] += __expf(fmaf(hi.x, SCALE, -SCALE));                  \
            sums[pi][1] += __expf(fmaf(hi.y, SCALE, -SCALE));                  \
        }                                                                      \
    }

#define FLUSH(nst)                                                             \
    {                                                                          \
        _Pragma("unroll")                                                      \
        for (int i = 0; i < 4; ++i) {                                          \
            float s0 = sums[i][0], s1 = sums[i][1];                            \
            s0 += __shfl_xor_sync(0xffffffffu, s0, 1);                         \
            s0 += __shfl_xor_sync(0xffffffffu, s0, 2);                         \
            s1 += __shfl_xor_sync(0xffffffffu, s1, 1);                         \
            s1 += __shfl_xor_sync(0xffffffffu, s1, 2);                         \
            if (qc == 0) {                                                     \
                int r = (nst) * BTN + wy * 64 + i * 16 + qr;                   \
                atomicAdd(&g_rowsum[r], s0);                                   \
                atomicAdd(&g_rowsum[r + 8], s1);                               \
            }                                                                  \
            sums[i][0] = 0.f; sums[i][1] = 0.f;                                \
        }                                                                      \
    }

// ---------------- kernel 2: persistent fp16 mma GEMM, full double-buffer ----------------
__global__ void __launch_bounds__(256, 1) k_main() {
    extern __shared__ char sh[];
    const uint32_t tb = (uint32_t)__cvta_generic_to_shared(sh);

    const int tid  = threadIdx.x;
    const int lane = tid & 31;
    const int wid  = tid >> 5;
    const int wy   = wid >> 1;         // n block (64 rows), 0..3
    const int wx   = wid & 1;          // m block (64 cols), 0..1
    const int quad = lane >> 3, rw = lane & 7;
    const int qr   = lane >> 2, qc = lane & 3;

    const uint32_t offA = (uint32_t)(((quad & 1) * 8 + rw) * SROW + (quad >> 1) * 16);
    const uint32_t offB = (uint32_t)(((quad >> 1) * 8 + rw) * SROW + (quad & 1) * 16);
    const uint32_t aRow = (uint32_t)(wy * 64 * SROW);
    const uint32_t bRow = (uint32_t)(wx * 64 * SROW);

    const int c  = blockIdx.x;
    const int u0 = (c * NUNITS) / NCTA;
    const int u1 = ((c + 1) * NUNITS) / NCTA;

    // previous-unit accumulators (half2); -2.0h -> exp(50*(-2)-50) = 0
    uint32_t accP[4][8][2];
#pragma unroll
    for (int i = 0; i < 4; ++i)
#pragma unroll
        for (int cb = 0; cb < 8; ++cb) {
            accP[i][cb][0] = 0xC000C000u; accP[i][cb][1] = 0xC000C000u;
        }
    float sums[4][2];
#pragma unroll
    for (int i = 0; i < 4; ++i) { sums[i][0] = 0.f; sums[i][1] = 0.f; }

    int aBuf  = 0;
    int cur_n = u0 >> 6;
    int n_acc = -1;                    // stripe of accP contents (-1 = dummy)

    // prologue: load first A + first B, one group
    load_A_async(tb + OFF_A(0), g_ts_h, cur_n * BTN, tid);
    load_B_async(tb + OFF_B(u0 & 1), g_sq_h, (u0 & 63) * BTM, tid);
    cp_commit();

    for (int u = u0; u < u1; ++u) {
        const int n   = u >> 6;        // 64 m-tiles per n-stripe
        const int m   = u & 63;
        const int buf = u & 1;
        if (n != cur_n) { aBuf ^= 1; cur_n = n; }

        // prefetch unit u+1 (buffers guarded by previous iteration's end-sync)
        if (u + 1 < u1) {
            const int n2 = (u + 1) >> 6;
            if (n2 != n)
                load_A_async(tb + OFF_A(aBuf ^ 1), g_ts_h, n2 * BTN, tid);
            load_B_async(tb + OFF_B((u + 1) & 1), g_sq_h, ((u + 1) & 63) * BTM, tid);
        }
        cp_commit();
        cp_wait1();                    // current unit's tiles resident
        __syncthreads();

        const uint32_t aP = tb + OFF_A(aBuf) + aRow + offA;
        const uint32_t bP = tb + OFF_B(buf) + bRow + offB;

        uint32_t accC[4][8][2];
#pragma unroll
        for (int i = 0; i < 4; ++i)
#pragma unroll
            for (int cb = 0; cb < 8; ++cb) { accC[i][cb][0] = 0u; accC[i][cb][1] = 0u; }

#pragma unroll
        for (int kk = 0; kk < 8; ++kk) {
            const uint32_t ko = (uint32_t)(kk * 32);
            uint32_t a[4][4];
#pragma unroll
            for (int i = 0; i < 4; ++i)
                ldsm4(aP + i * (16 * SROW) + ko, a[i][0], a[i][1], a[i][2], a[i][3]);
#pragma unroll
            for (int j = 0; j < 4; ++j) {
                uint32_t b0, b1, b2, b3;
                ldsm4(bP + j * (16 * SROW) + ko, b0, b1, b2, b3);
#pragma unroll
                for (int i = 0; i < 4; ++i) {
                    mma16816h(accC[i][2 * j],     a[i], b0, b1);
                    mma16816h(accC[i][2 * j + 1], a[i], b2, b3);
                }
            }
            PREV_CHUNK(kk);            // previous unit's exp in the MMA shadow
        }

        // flush only at stripe boundary (atomics amortized 64x)
        if (n_acc >= 0 && n_acc != n) FLUSH(n_acc);
        n_acc = n;
#pragma unroll
        for (int i = 0; i < 4; ++i)
#pragma unroll
            for (int cb = 0; cb < 8; ++cb) {
                accP[i][cb][0] = accC[i][cb][0];
                accP[i][cb][1] = accC[i][cb][1];
            }
        __syncthreads();               // reads of buf done before next prefetch writes it
    }

    // drain: last unit's accumulators, then final flush
#pragma unroll
    for (int kk = 0; kk < 8; ++kk) PREV_CHUNK(kk);
    if (n_acc >= 0) FLUSH(n_acc);
}

// ---------------- kernel 3: lse + masked loss (+ fused div) ----------------
__global__ void __launch_bounds__(256) k_final(const int* __restrict__ pmask,
                                               float* __restrict__ out) {
    __shared__ double s_loss[256];
    __shared__ float  s_pm[256];
    __shared__ int    s_last;
    const int tid = threadIdx.x;
    const int n   = blockIdx.x * 256 + tid;

    float d   = g_diag[n];
    float lse = SCALE + logf(g_rowsum[n]);
    float pm  = (float)pmask[n];

    s_loss[tid] = (double)(pm * (d - lse));
    s_pm[tid]   = pm;
    __syncthreads();
    for (int o = 128; o; o >>= 1) {
        if (tid < o) { s_loss[tid] += s_loss[tid + o]; s_pm[tid] += s_pm[tid + o]; }
        __syncthreads();
    }
    if (tid == 0) {
        atomicAdd(&g_acc[0], s_loss[0]);
        atomicAdd(&g_acc[1], (double)s_pm[0]);
        __threadfence();
        unsigned int v = atomicAdd(&g_cnt, 1u);
        s_last = (v == (unsigned int)(gridDim.x - 1)) ? 1 : 0;
    }
    __syncthreads();
    if (s_last && tid == 0)
        out[0] = (float)(-g_acc[0] / (g_acc[1] + 1e-6));
}

extern "C" void kernel_launch(void* const* d_in, const int* in_sizes, int n_in,
                              void* d_out, int out_size) {
    const float* ts = (const float*)d_in[0];
    const float* sq = (const float*)d_in[1];
    const int*   pm = (const int*)d_in[3];
    float* out = (float*)d_out;

    cudaFuncSetAttribute(k_main, cudaFuncAttributeMaxDynamicSharedMemorySize, SMEM_BYTES);

    k_norm<<<NN / 32, 256>>>(ts, sq);
    k_main<<<NCTA, 256, SMEM_BYTES>>>();
    k_final<<<NN / 256, 256>>>(pm, out);
}

// round 16
// speedup vs baseline: 1.0648x; 1.0648x over previous
#include <cuda_runtime.h>
#include <cuda_fp16.h>
#include <cstdint>

// Problem constants
#define NN      8192
#define DD      128
#define BTN     256                // CTA tile rows (n)
#define BTM     128                // CTA tile cols (m)
#define NTN     (NN / BTN)         // 32
#define NTM     (NN / BTM)         // 64
#define NUNITS  (NTN * NTM)        // 2048
#define NCTA    148
#define SCALE   50.0f

// SMEM geometry: padded row stride 272 bytes (136 fp16)
#define SROW    272
#define TA      (BTN * SROW)       // 69632
#define TBB     (BTM * SROW)       // 34816
#define OFF_A     0
#define OFF_B(buf)  (TA + (buf) * TBB)
#define SMEM_BYTES (TA + 2 * TBB)  // 139264

// Static device scratch
__device__ __half g_ts_h[NN * DD];
__device__ __half g_sq_h[NN * DD];
__device__ float  g_diag[NN];        // 50 * <ts_n, sq_n> (fp32 exact)
__device__ float  g_rowsum[NN];
__device__ double g_acc[2];
__device__ unsigned int g_cnt;

// ---------------- PTX helpers ----------------
__device__ __forceinline__ void cp16(uint32_t saddr, const void* g) {
    asm volatile("cp.async.cg.shared.global [%0], [%1], 16;" :: "r"(saddr), "l"(g));
}
__device__ __forceinline__ void cp_commit() { asm volatile("cp.async.commit_group;"); }
__device__ __forceinline__ void cp_wait0()  { asm volatile("cp.async.wait_group 0;"); }
__device__ __forceinline__ void cp_wait1()  { asm volatile("cp.async.wait_group 1;"); }

__device__ __forceinline__ void ldsm4(uint32_t a, uint32_t& r0, uint32_t& r1,
                                      uint32_t& r2, uint32_t& r3) {
    asm volatile("ldmatrix.sync.aligned.m8n8.x4.shared.b16 {%0,%1,%2,%3}, [%4];"
                 : "=r"(r0), "=r"(r1), "=r"(r2), "=r"(r3) : "r"(a));
}
// fp16-accumulate HMMA
__device__ __forceinline__ void mma16816h(uint32_t* c, const uint32_t* a,
                                          uint32_t b0, uint32_t b1) {
    asm volatile("mma.sync.aligned.m16n8k16.row.col.f16.f16.f16.f16 "
                 "{%0,%1}, {%2,%3,%4,%5}, {%6,%7}, {%0,%1};"
                 : "+r"(c[0]), "+r"(c[1])
                 : "r"(a[0]), "r"(a[1]), "r"(a[2]), "r"(a[3]), "r"(b0), "r"(b1));
}
__device__ __forceinline__ float2 h2_to_f2(uint32_t u) {
    float2 r;
    asm("{\n\t.reg .f16 h0, h1;\n\t"
        "mov.b32 {h0, h1}, %2;\n\t"
        "cvt.f32.f16 %0, h0;\n\t"
        "cvt.f32.f16 %1, h1;\n\t}" : "=f"(r.x), "=f"(r.y) : "r"(u));
    return r;
}

// ---------------- kernel 1: normalize (2 rows/warp) + fp16 out + exact diag ----------------
// 512 blocks x 8 warps x 2 rows = 8192 rows; each warp handles BOTH matrices.
__global__ void __launch_bounds__(256) k_norm(const float* __restrict__ ts,
                                              const float* __restrict__ sq) {
    const int tid = threadIdx.x;
    if (blockIdx.x < 8) {   // zero accumulators
        reinterpret_cast<float4*>(g_rowsum)[blockIdx.x * 256 + tid] =
            make_float4(0.f, 0.f, 0.f, 0.f);
        if (blockIdx.x == 0 && tid == 0) {
            g_acc[0] = 0.0; g_acc[1] = 0.0; g_cnt = 0u;
        }
    }
    const int n0   = blockIdx.x * 16 + (tid >> 5) * 2;
    const int lane = tid & 31;

    float4 a0 = reinterpret_cast<const float4*>(ts + (size_t)n0 * DD)[lane];
    float4 b0 = reinterpret_cast<const float4*>(sq + (size_t)n0 * DD)[lane];
    float4 a1 = reinterpret_cast<const float4*>(ts + (size_t)(n0 + 1) * DD)[lane];
    float4 b1 = reinterpret_cast<const float4*>(sq + (size_t)(n0 + 1) * DD)[lane];

    float st0 = a0.x * a0.x + a0.y * a0.y + a0.z * a0.z + a0.w * a0.w;
    float sq0 = b0.x * b0.x + b0.y * b0.y + b0.z * b0.z + b0.w * b0.w;
    float dt0 = a0.x * b0.x + a0.y * b0.y + a0.z * b0.z + a0.w * b0.w;
    float st1 = a1.x * a1.x + a1.y * a1.y + a1.z * a1.z + a1.w * a1.w;
    float sq1 = b1.x * b1.x + b1.y * b1.y + b1.z * b1.z + b1.w * b1.w;
    float dt1 = a1.x * b1.x + a1.y * b1.y + a1.z * b1.z + a1.w * b1.w;
#pragma unroll
    for (int o = 16; o; o >>= 1) {
        st0 += __shfl_xor_sync(0xffffffffu, st0, o);
        sq0 += __shfl_xor_sync(0xffffffffu, sq0, o);
        dt0 += __shfl_xor_sync(0xffffffffu, dt0, o);
        st1 += __shfl_xor_sync(0xffffffffu, st1, o);
        sq1 += __shfl_xor_sync(0xffffffffu, sq1, o);
        dt1 += __shfl_xor_sync(0xffffffffu, dt1, o);
    }
    float it0 = 1.0f / fmaxf(sqrtf(st0), 1e-12f);
    float is0 = 1.0f / fmaxf(sqrtf(sq0), 1e-12f);
    float it1 = 1.0f / fmaxf(sqrtf(st1), 1e-12f);
    float is1 = 1.0f / fmaxf(sqrtf(sq1), 1e-12f);

    size_t e0 = (size_t)n0 * DD + lane * 4;
    size_t e1 = e0 + DD;
    *reinterpret_cast<__half2*>(g_ts_h + e0)     = __floats2half2_rn(a0.x * it0, a0.y * it0);
    *reinterpret_cast<__half2*>(g_ts_h + e0 + 2) = __floats2half2_rn(a0.z * it0, a0.w * it0);
    *reinterpret_cast<__half2*>(g_sq_h + e0)     = __floats2half2_rn(b0.x * is0, b0.y * is0);
    *reinterpret_cast<__half2*>(g_sq_h + e0 + 2) = __floats2half2_rn(b0.z * is0, b0.w * is0);
    *reinterpret_cast<__half2*>(g_ts_h + e1)     = __floats2half2_rn(a1.x * it1, a1.y * it1);
    *reinterpret_cast<__half2*>(g_ts_h + e1 + 2) = __floats2half2_rn(a1.z * it1, a1.w * it1);
    *reinterpret_cast<__half2*>(g_sq_h + e1)     = __floats2half2_rn(b1.x * is1, b1.y * is1);
    *reinterpret_cast<__half2*>(g_sq_h + e1 + 2) = __floats2half2_rn(b1.z * is1, b1.w * is1);
    if (lane == 0) {
        g_diag[n0]     = dt0 * it0 * is0 * SCALE;
        g_diag[n0 + 1] = dt1 * it1 * is1 * SCALE;
    }
}

// ---------------- tile loaders (256 threads) ----------------
__device__ __forceinline__ void load_A_async(uint32_t s_dst, const __half* g,
                                             int row0, int tid) {
#pragma unroll
    for (int it = 0; it < 16; ++it) {
        int ch  = tid + it * 256;
        int r   = ch >> 4;
        int c16 = ch & 15;
        cp16(s_dst + (uint32_t)(r * SROW + c16 * 16),
             g + (size_t)(row0 + r) * DD + c16 * 8);
    }
}
__device__ __forceinline__ void load_B_async(uint32_t s_dst, const __half* g,
                                             int row0, int tid) {
#pragma unroll
    for (int it = 0; it < 8; ++it) {
        int ch  = tid + it * 256;
        int r   = ch >> 4;
        int c16 = ch & 15;
        cp16(s_dst + (uint32_t)(r * SROW + c16 * 16),
             g + (size_t)(row0 + r) * DD + c16 * 8);
    }
}

// process 1/8 of the previous unit's accumulators
#define PREV_CHUNK(kk)                                                         \
    {                                                                          \
        const int pi = (kk) >> 1, pc0 = ((kk) & 1) * 4;                        \
        _Pragma("unroll")                                                      \
        for (int cb = 0; cb < 4; ++cb) {                                       \
            float2 lo = h2_to_f2(accP[pi][pc0 + cb][0]);                       \
            float2 hi = h2_to_f2(accP[pi][pc0 + cb][1]);                       \
            sums[pi][0] += __expf(fmaf(lo.x, SCALE, -SCALE));                  \
            sums[pi][0] += __expf(fmaf(lo.y, SCALE, -SCALE));                  \
            sums[pi][1] += __expf(fmaf(hi.x, SCALE, -SCALE));                  \
            sums[pi][1] += __expf(fmaf(hi.y, SCALE, -SCALE));                  \
        }                                                                      \
    }

#define FLUSH(nst)                                                             \
    {                                                                          \
        _Pragma("unroll")                                                      \
        for (int i = 0; i < 4; ++i) {                                          \
            float s0 = sums[i][0], s1 = sums[i][1];                            \
            s0 += __shfl_xor_sync(0xffffffffu, s0, 1);                         \
            s0 += __shfl_xor_sync(0xffffffffu, s0, 2);                         \
            s1 += __shfl_xor_sync(0xffffffffu, s1, 1);                         \
            s1 += __shfl_xor_sync(0xffffffffu, s1, 2);                         \
            if (qc == 0) {                                                     \
                int r = (nst) * BTN + wy * 64 + i * 16 + qr;                   \
                atomicAdd(&g_rowsum[r], s0);                                   \
                atomicAdd(&g_rowsum[r + 8], s1);                               \
            }                                                                  \
            sums[i][0] = 0.f; sums[i][1] = 0.f;                                \
        }                                                                      \
    }

// ---------------- kernel 2: persistent fp16 mma GEMM, per-stripe flush (R12) ----------------
__global__ void __launch_bounds__(256, 1) k_main() {
    extern __shared__ char sh[];
    const uint32_t tb = (uint32_t)__cvta_generic_to_shared(sh);

    const int tid  = threadIdx.x;
    const int lane = tid & 31;
    const int wid  = tid >> 5;
    const int wy   = wid >> 1;         // n block (64 rows), 0..3
    const int wx   = wid & 1;          // m block (64 cols), 0..1
    const int quad = lane >> 3, rw = lane & 7;
    const int qr   = lane >> 2, qc = lane & 3;

    const uint32_t offA = (uint32_t)(((quad & 1) * 8 + rw) * SROW + (quad >> 1) * 16);
    const uint32_t offB = (uint32_t)(((quad >> 1) * 8 + rw) * SROW + (quad & 1) * 16);
    const uint32_t aRow = (uint32_t)(wy * 64 * SROW);
    const uint32_t bRow = (uint32_t)(wx * 64 * SROW);

    const int c  = blockIdx.x;
    const int u0 = (c * NUNITS) / NCTA;
    const int u1 = ((c + 1) * NUNITS) / NCTA;

    // previous-unit accumulators (half2); -2.0h -> exp(50*(-2)-50) = 0
    uint32_t accP[4][8][2];
#pragma unroll
    for (int i = 0; i < 4; ++i)
#pragma unroll
        for (int cb = 0; cb < 8; ++cb) {
            accP[i][cb][0] = 0xC000C000u; accP[i][cb][1] = 0xC000C000u;
        }
    float sums[4][2];
#pragma unroll
    for (int i = 0; i < 4; ++i) { sums[i][0] = 0.f; sums[i][1] = 0.f; }

    int cur_n = -1;
    int n_acc = -1;                    // stripe of accP contents (-1 = dummy)

    for (int u = u0; u < u1; ++u) {
        const int n   = u >> 6;        // 64 m-tiles per n-stripe
        const int m   = u & 63;
        const int buf = u & 1;

        if (n != cur_n) {
            __syncthreads();
            load_A_async(tb + OFF_A, g_ts_h, n * BTN, tid);
            load_B_async(tb + OFF_B(buf), g_sq_h, m * BTM, tid);
            cp_commit();
            cp_wait0();
            cur_n = n;
        }
        if (u + 1 < u1 && ((u + 1) >> 6) == n) {
            load_B_async(tb + OFF_B(buf ^ 1), g_sq_h, ((u + 1) & 63) * BTM, tid);
        }
        cp_commit();
        cp_wait1();
        __syncthreads();

        const uint32_t aP = tb + OFF_A + aRow + offA;
        const uint32_t bP = tb + OFF_B(buf) + bRow + offB;

        uint32_t accC[4][8][2];
#pragma unroll
        for (int i = 0; i < 4; ++i)
#pragma unroll
            for (int cb = 0; cb < 8; ++cb) { accC[i][cb][0] = 0u; accC[i][cb][1] = 0u; }

#pragma unroll
        for (int kk = 0; kk < 8; ++kk) {
            const uint32_t ko = (uint32_t)(kk * 32);
            uint32_t a[4][4];
#pragma unroll
            for (int i = 0; i < 4; ++i)
                ldsm4(aP + i * (16 * SROW) + ko, a[i][0], a[i][1], a[i][2], a[i][3]);
#pragma unroll
            for (int j = 0; j < 4; ++j) {
                uint32_t b0, b1, b2, b3;
                ldsm4(bP + j * (16 * SROW) + ko, b0, b1, b2, b3);
#pragma unroll
                for (int i = 0; i < 4; ++i) {
                    mma16816h(accC[i][2 * j],     a[i], b0, b1);
                    mma16816h(accC[i][2 * j + 1], a[i], b2, b3);
                }
            }
            PREV_CHUNK(kk);            // previous unit's exp in the MMA shadow
        }

        // flush only at stripe boundary (atomics amortized 64x)
        if (n_acc >= 0 && n_acc != n) FLUSH(n_acc);
        n_acc = n;
#pragma unroll
        for (int i = 0; i < 4; ++i)
#pragma unroll
            for (int cb = 0; cb < 8; ++cb) {
                accP[i][cb][0] = accC[i][cb][0];
                accP[i][cb][1] = accC[i][cb][1];
            }
        __syncthreads();
    }

    // drain: last unit's accumulators, then final flush
#pragma unroll
    for (int kk = 0; kk < 8; ++kk) PREV_CHUNK(kk);
    if (n_acc >= 0) FLUSH(n_acc);
}

// ---------------- kernel 3: lse + masked loss (+ fused div) ----------------
__global__ void __launch_bounds__(256) k_final(const int* __restrict__ pmask,
                                               float* __restrict__ out) {
    __shared__ double s_loss[256];
    __shared__ float  s_pm[256];
    __shared__ int    s_last;
    const int tid = threadIdx.x;
    const int n   = blockIdx.x * 256 + tid;

    float d   = g_diag[n];
    float lse = SCALE + logf(g_rowsum[n]);
    float pm  = (float)pmask[n];

    s_loss[tid] = (double)(pm * (d - lse));
    s_pm[tid]   = pm;
    __syncthreads();
    for (int o = 128; o; o >>= 1) {
        if (tid < o) { s_loss[tid] += s_loss[tid + o]; s_pm[tid] += s_pm[tid + o]; }
        __syncthreads();
    }
    if (tid == 0) {
        atomicAdd(&g_acc[0], s_loss[0]);
        atomicAdd(&g_acc[1], (double)s_pm[0]);
        __threadfence();
        unsigned int v = atomicAdd(&g_cnt, 1u);
        s_last = (v == (unsigned int)(gridDim.x - 1)) ? 1 : 0;
    }
    __syncthreads();
    if (s_last && tid == 0)
        out[0] = (float)(-g_acc[0] / (g_acc[1] + 1e-6));
}

extern "C" void kernel_launch(void* const* d_in, const int* in_sizes, int n_in,
                              void* d_out, int out_size) {
    const float* ts = (const float*)d_in[0];
    const float* sq = (const float*)d_in[1];
    const int*   pm = (const int*)d_in[3];
    float* out = (float*)d_out;

    cudaFuncSetAttribute(k_main, cudaFuncAttributeMaxDynamicSharedMemorySize, SMEM_BYTES);

    k_norm<<<NN / 16, 256>>>(ts, sq);
    k_main<<<NCTA, 256, SMEM_BYTES>>>();
    k_final<<<NN / 256, 256>>>(pm, out);
}